// round 13
// baseline (speedup 1.0000x reference)
#include <cuda_runtime.h>
#include <math.h>

#define NN    4096
#define FIN   512
#define HIDN  256
#define RRE   16
#define EE    65536
#define BBS   32
#define SSEQ  128
#define DHH   768
#define DD2   1536
#define GG4   3072

typedef unsigned long long u64;
typedef unsigned int u32;

// ---------------- tf32 helpers ----------------
__device__ __forceinline__ u32 cvtf(float x) {
    u32 r; asm("cvt.rna.tf32.f32 %0, %1;" : "=r"(r) : "f"(x)); return r;
}
__device__ __forceinline__ void split_tf32(float x, u32& hi, u32& lo) {
    hi = cvtf(x);
    lo = cvtf(x - __uint_as_float(hi));
}
__device__ __forceinline__ void mma8(float* d, const u32* a, const u32* b) {
    asm("mma.sync.aligned.m16n8k8.row.col.f32.tf32.tf32.f32 "
        "{%0,%1,%2,%3}, {%4,%5,%6,%7}, {%8,%9}, {%0,%1,%2,%3};"
        : "+f"(d[0]), "+f"(d[1]), "+f"(d[2]), "+f"(d[3])
        : "r"(a[0]), "r"(a[1]), "r"(a[2]), "r"(a[3]), "r"(b[0]), "r"(b[1]));
}
__device__ __forceinline__ void cpa16(u32 dst, const void* src) {
    asm volatile("cp.async.ca.shared.global [%0], [%1], 16;" :: "r"(dst), "l"(src) : "memory");
}

// ---------------- device scratch ----------------
__device__ float g_hrel[(size_t)RRE * NN * HIDN];
__device__ float g_out1[(size_t)NN * HIDN];
__device__ float g_cnt[(size_t)NN * RRE];
__device__ float g_agg[(size_t)NN * HIDN];
__device__ float g_out2[(size_t)NN * HIDN];
__device__ float g_x0[(size_t)NN * DHH];
__device__ float g_g0[(size_t)2 * NN * GG4];
__device__ float g_h0[(size_t)NN * DD2];
__device__ float g_g1[(size_t)2 * NN * GG4];
__device__ float g_M[(size_t)NN * DD2];
__device__ float g_X[(size_t)NN * DD2];
__device__ float g_att[(size_t)NN * DD2];
__device__ u32 g_whi[(size_t)2 * GG4 * DHH];      // Whh tf32 hi (LSTM)
__device__ u32 g_wlo[(size_t)2 * GG4 * DHH];      // Whh tf32 lo (LSTM)
__device__ float g_hf[(size_t)2 * 2 * BBS * DHH]; // h state
__device__ u64 g_as[(size_t)NN * DD2];            // packed pre-split A (max 6.3M)
__device__ u64 g_bs[(size_t)2 * GG4 * DD2];       // packed pre-split B (max 9.4M)
__device__ unsigned g_bar[2];

__global__ void fill_zero_kernel(float* p, int n) {
    int i = blockIdx.x * 256 + threadIdx.x;
    if (i < n) p[i] = 0.0f;
}

__device__ __forceinline__ float sigf(float x) { return 1.0f / (1.0f + expf(-x)); }

// pre-split f32 -> packed (hi | lo<<32)
__global__ void wsplit2_kernel(const float* __restrict__ W, u64* __restrict__ Ws, int n) {
    int i = blockIdx.x * 256 + threadIdx.x;
    if (i < n) {
        u32 h, l; split_tf32(W[i], h, l);
        Ws[i] = ((u64)l << 32) | h;
    }
}

// ---------------- 3xTF32 GEMM on pre-split packed operands -------------------
// C[M,N] = act(A @ (TRANSB ? B^T : B) + bias + (addC ? C : 0)), z-batched.
// A,B are packed u64 (hi|lo). M mult 128, N mult 64, K mult 16.
#define AST 18                    // A smem row stride (u64)
#define BST_T 18                  // B smem row stride, TRANSB ([64][18])
#define BST_N 66                  // B smem row stride, non-TRANSB ([16][66])
#define ABUF (128 * AST)
#define BBUF 1152
#define SMEM_GEMM ((2 * ABUF + 2 * BBUF) * 8)

template<bool TRANSB, bool RELU>
__global__ __launch_bounds__(256, 2) void tgemm_kernel(
    const u64* __restrict__ A, const u64* __restrict__ B,
    const float* __restrict__ bias, float* __restrict__ C,
    int M, int N, int K,
    size_t sA, size_t sB, size_t sBias, size_t sC, int addC)
{
    A += (size_t)blockIdx.z * sA;
    B += (size_t)blockIdx.z * sB;
    C += (size_t)blockIdx.z * sC;
    const float* bi = bias ? bias + (size_t)blockIdx.z * sBias : (const float*)0;

    extern __shared__ u64 dyn[];
    u64* Asm = dyn;                 // [2][128][AST]
    u64* Bsm = dyn + 2 * ABUF;      // [2][BBUF]

    const int m0 = blockIdx.y * 128, n0 = blockIdx.x * 64;
    const int tid = threadIdx.x;
    const int lane = tid & 31, wid = tid >> 5;
    const int wm = (wid & 3) * 32, wn = (wid >> 2) * 32;
    const int g = lane >> 2, tig = lane & 3;
    const int KT = K >> 4;

    const u32 sA0 = (u32)__cvta_generic_to_shared(Asm);
    const u32 sB0 = (u32)__cvta_generic_to_shared(Bsm);

    float acc[2][4][4];
#pragma unroll
    for (int mt = 0; mt < 2; mt++)
#pragma unroll
        for (int nt = 0; nt < 4; nt++)
#pragma unroll
            for (int q = 0; q < 4; q++) acc[mt][nt][q] = 0.0f;

    auto issue = [&](int kt, int buf) {
        const int k0 = kt * 16;
        u32 da = sA0 + buf * (ABUF * 8);
#pragma unroll
        for (int i = 0; i < 4; i++) {   // A: 1024 16B-chunks, 4/thread
            int q = tid + i * 256;
            int ar = q >> 3, ac = (q & 7) * 2;
            cpa16(da + (ar * AST + ac) * 8, A + (size_t)(m0 + ar) * K + k0 + ac);
        }
        u32 db = sB0 + buf * (BBUF * 8);
        if (TRANSB) {                    // B [N,K]: 512 chunks, 2/thread
#pragma unroll
            for (int i = 0; i < 2; i++) {
                int q = tid + i * 256;
                int br = q >> 3, bc = (q & 7) * 2;
                cpa16(db + (br * BST_T + bc) * 8, B + (size_t)(n0 + br) * K + k0 + bc);
            }
        } else {                         // B [K,N]: 512 chunks, 2/thread
#pragma unroll
            for (int i = 0; i < 2; i++) {
                int q = tid + i * 256;
                int bk = q >> 5, bn = (q & 31) * 2;
                cpa16(db + (bk * BST_N + bn) * 8, B + (size_t)(k0 + bk) * N + n0 + bn);
            }
        }
        asm volatile("cp.async.commit_group;" ::: "memory");
    };

    issue(0, 0);
    for (int kt = 0; kt < KT; kt++) {
        const int buf = kt & 1;
        if (kt + 1 < KT) {
            issue(kt + 1, buf ^ 1);
            asm volatile("cp.async.wait_group 1;" ::: "memory");
        } else {
            asm volatile("cp.async.wait_group 0;" ::: "memory");
        }
        __syncthreads();

        const u64* Ab = Asm + buf * ABUF;
        const u64* Bb = Bsm + buf * BBUF;
#pragma unroll
        for (int ks = 0; ks < 2; ks++) {
            const int kb = ks * 8;
            u32 afh[2][4], afl[2][4], bfh[4][2], bfl[4][2];
#pragma unroll
            for (int mt = 0; mt < 2; mt++) {
                int r = wm + mt * 16 + g;
                u64 v0 = Ab[r * AST + kb + tig];
                u64 v1 = Ab[(r + 8) * AST + kb + tig];
                u64 v2 = Ab[r * AST + kb + tig + 4];
                u64 v3 = Ab[(r + 8) * AST + kb + tig + 4];
                afh[mt][0] = (u32)v0; afl[mt][0] = (u32)(v0 >> 32);
                afh[mt][1] = (u32)v1; afl[mt][1] = (u32)(v1 >> 32);
                afh[mt][2] = (u32)v2; afl[mt][2] = (u32)(v2 >> 32);
                afh[mt][3] = (u32)v3; afl[mt][3] = (u32)(v3 >> 32);
            }
#pragma unroll
            for (int nt = 0; nt < 4; nt++) {
                int c = wn + nt * 8 + g;
                u64 w0 = TRANSB ? Bb[c * BST_T + kb + tig]     : Bb[(kb + tig) * BST_N + c];
                u64 w1 = TRANSB ? Bb[c * BST_T + kb + tig + 4] : Bb[(kb + tig + 4) * BST_N + c];
                bfh[nt][0] = (u32)w0; bfl[nt][0] = (u32)(w0 >> 32);
                bfh[nt][1] = (u32)w1; bfl[nt][1] = (u32)(w1 >> 32);
            }
#pragma unroll
            for (int mt = 0; mt < 2; mt++)
#pragma unroll
                for (int nt = 0; nt < 4; nt++) {
                    mma8(acc[mt][nt], afl[mt], bfh[nt]);
                    mma8(acc[mt][nt], afh[mt], bfl[nt]);
                    mma8(acc[mt][nt], afh[mt], bfh[nt]);
                }
        }
        __syncthreads();
    }
#pragma unroll
    for (int mt = 0; mt < 2; mt++) {
#pragma unroll
        for (int nt = 0; nt < 4; nt++) {
            int c = n0 + wn + nt * 8 + 2 * tig;
#pragma unroll
            for (int h = 0; h < 2; h++) {
                int r = m0 + wm + mt * 16 + g + h * 8;
                float2 v = make_float2(acc[mt][nt][h * 2], acc[mt][nt][h * 2 + 1]);
                if (bi) { v.x += bi[c]; v.y += bi[c + 1]; }
                float2* cp = (float2*)&C[(size_t)r * N + c];
                if (addC) { float2 o = *cp; v.x += o.x; v.y += o.y; }
                if (RELU) { v.x = fmaxf(v.x, 0.f); v.y = fmaxf(v.y, 0.f); }
                *cp = v;
            }
        }
    }
}

// ---------------- graph kernels ----------------
__global__ void count_kernel(const int* __restrict__ ei, const int* __restrict__ et,
                             float* __restrict__ cnt) {
    int e = blockIdx.x * 256 + threadIdx.x;
    if (e < EE) atomicAdd(&cnt[ei[EE + e] * RRE + et[e]], 1.0f);
}

__global__ void rgcn_scatter_kernel(const float* __restrict__ hrel, const int* __restrict__ ei,
                                    const int* __restrict__ et, const float* __restrict__ cnt,
                                    float* __restrict__ out1) {
    int e = blockIdx.x * 4 + (threadIdx.x >> 6);
    int lane = threadIdx.x & 63;
    int src = ei[e], dst = ei[EE + e], r = et[e];
    float inv = 1.0f / fmaxf(cnt[dst * RRE + r], 1.0f);
    float4 v = ((const float4*)(hrel + ((size_t)r * NN + src) * HIDN))[lane];
    float* o = out1 + (size_t)dst * HIDN + lane * 4;
    atomicAdd(o + 0, v.x * inv);
    atomicAdd(o + 1, v.y * inv);
    atomicAdd(o + 2, v.z * inv);
    atomicAdd(o + 3, v.w * inv);
}

__global__ void gconv_scatter_kernel(const float* __restrict__ out1, const int* __restrict__ ei,
                                     float* __restrict__ agg) {
    int e = blockIdx.x * 4 + (threadIdx.x >> 6);
    int lane = threadIdx.x & 63;
    int src = ei[e], dst = ei[EE + e];
    float4 v = ((const float4*)(out1 + (size_t)src * HIDN))[lane];
    float* o = agg + (size_t)dst * HIDN + lane * 4;
    atomicAdd(o + 0, v.x);
    atomicAdd(o + 1, v.y);
    atomicAdd(o + 2, v.z);
    atomicAdd(o + 3, v.w);
}

__global__ void concat_kernel(const float* __restrict__ feat, const float* __restrict__ out2,
                              float* __restrict__ x0) {
    int n = blockIdx.x;
    int b = n >> 7, s = n & 127;
    float* dstrow = x0 + (size_t)(s * BBS + b) * DHH;
    for (int d = threadIdx.x; d < DHH; d += 256)
        dstrow[d] = (d < FIN) ? feat[(size_t)n * FIN + d] : out2[(size_t)n * HIDN + (d - FIN)];
}

// ---------------- persistent tensor-core BiLSTM (unchanged from R12) --------
#define NBLK 128
#define WST  772
#define PCOLS 52
#define SMEM_TLSTM ((48 * WST + 8 * 32 * PCOLS) * 4)

__device__ __forceinline__ void gbar(unsigned phase) {
    __syncthreads();
    if (threadIdx.x == 0) {
        __threadfence();
        unsigned a = atomicAdd(&g_bar[0], 1u);
        if (a == NBLK - 1u) {
            g_bar[0] = 0u;
            __threadfence();
            atomicExch(&g_bar[1], phase + 1u);
        } else {
            volatile unsigned* gen = &g_bar[1];
            while (*gen <= phase) __nanosleep(32);
        }
        __threadfence();
    }
    __syncthreads();
}

__global__ void wsplit_kernel(const float* __restrict__ W, u32* __restrict__ whi,
                              u32* __restrict__ wlo, int n) {
    int i = blockIdx.x * 256 + threadIdx.x;
    if (i < n) {
        u32 h, l; split_tf32(W[i], h, l);
        whi[i] = h; wlo[i] = l;
    }
}

__global__ __launch_bounds__(256) void lstm_tc_kernel(
    const u32* __restrict__ Whi, const u32* __restrict__ Wlo,
    const float* __restrict__ gpre,
    float* __restrict__ hf, float* __restrict__ hout)
{
    extern __shared__ u32 smu[];
    u32* whi = smu;
    float* part = (float*)(smu + 48 * WST);

    const int bx = blockIdx.x;
    const int dir = bx & 1;
    const int j0 = (bx >> 1) * 12;
    const int tid = threadIdx.x;
    const int w = tid >> 5, lane = tid & 31;
    const int g = lane >> 2, tig = lane & 3;

    const u32* WhiG = Whi + (size_t)dir * GG4 * DHH;
    const u32* WloG = Wlo + (size_t)dir * GG4 * DHH;

    for (int idx = tid; idx < 48 * DHH; idx += 256) {
        int c = idx / DHH, k = idx % DHH;
        int row = (c / 12) * DHH + j0 + (c % 12);
        whi[c * WST + k] = WhiG[(size_t)row * DHH + k];
    }
    const u32* wlop[6];
    int ccol[6];
#pragma unroll
    for (int nt = 0; nt < 6; nt++) {
        int c = nt * 8 + g;
        int row = (c / 12) * DHH + j0 + (c % 12);
        wlop[nt] = WloG + (size_t)row * DHH;
        ccol[nt] = c;
    }
    __syncthreads();

    float cst[2] = {0.0f, 0.0f};

    for (int t = 0; t < SSEQ; t++) {
        const float* hin = hf + ((size_t)(t & 1) * 2 + dir) * (BBS * DHH);
        float* hOut      = hf + ((size_t)((t + 1) & 1) * 2 + dir) * (BBS * DHH);

        float acc[2][6][4];
#pragma unroll
        for (int mt = 0; mt < 2; mt++)
#pragma unroll
            for (int nt = 0; nt < 6; nt++)
#pragma unroll
                for (int q = 0; q < 4; q++) acc[mt][nt][q] = 0.0f;

        const int kw = w * 96;
#pragma unroll
        for (int s = 0; s < 12; s++) {
            const int k0 = kw + s * 8;
            u32 ah[2][4], al[2][4];
#pragma unroll
            for (int mt = 0; mt < 2; mt++) {
                int r0 = mt * 16 + g;
                float f0 = hin[r0 * DHH + k0 + tig];
                float f1 = hin[(r0 + 8) * DHH + k0 + tig];
                float f2 = hin[r0 * DHH + k0 + tig + 4];
                float f3 = hin[(r0 + 8) * DHH + k0 + tig + 4];
                split_tf32(f0, ah[mt][0], al[mt][0]);
                split_tf32(f1, ah[mt][1], al[mt][1]);
                split_tf32(f2, ah[mt][2], al[mt][2]);
                split_tf32(f3, ah[mt][3], al[mt][3]);
            }
#pragma unroll
            for (int nt = 0; nt < 6; nt++) {
                u32 bh[2], bl[2];
                bh[0] = whi[ccol[nt] * WST + k0 + tig];
                bh[1] = whi[ccol[nt] * WST + k0 + tig + 4];
                bl[0] = wlop[nt][k0 + tig];
                bl[1] = wlop[nt][k0 + tig + 4];
#pragma unroll
                for (int mt = 0; mt < 2; mt++) {
                    mma8(acc[mt][nt], al[mt], bh);
                    mma8(acc[mt][nt], ah[mt], bl);
                    mma8(acc[mt][nt], ah[mt], bh);
                }
            }
        }
#pragma unroll
        for (int mt = 0; mt < 2; mt++)
#pragma unroll
            for (int nt = 0; nt < 6; nt++) {
                int b0 = mt * 16 + g, c = nt * 8 + 2 * tig;
                float* p0 = &part[(w * 32 + b0) * PCOLS + c];
                p0[0] = acc[mt][nt][0]; p0[1] = acc[mt][nt][1];
                float* p1 = &part[(w * 32 + b0 + 8) * PCOLS + c];
                p1[0] = acc[mt][nt][2]; p1[1] = acc[mt][nt][3];
            }
        __syncthreads();
        const int tdir = dir ? (SSEQ - 1 - t) : t;
#pragma unroll
        for (int u = 0; u < 2; u++) {
            int pr = tid + u * 256;
            if (pr < 384) {
                int b = pr / 12, jl = pr % 12;
                int j = j0 + jl;
                int row = tdir * BBS + b;
                const float* gp = gpre + ((size_t)dir * NN + row) * GG4;
                float gi = 0.f, gf = 0.f, gg = 0.f, go = 0.f;
#pragma unroll
                for (int ww = 0; ww < 8; ww++) {
                    const float* p = &part[(ww * 32 + b) * PCOLS];
                    gi += p[jl];
                    gf += p[12 + jl];
                    gg += p[24 + jl];
                    go += p[36 + jl];
                }
                gi += gp[j];
                gf += gp[DHH + j];
                gg += gp[2 * DHH + j];
                go += gp[3 * DHH + j];
                float c2 = sigf(gf) * cst[u] + sigf(gi) * tanhf(gg);
                cst[u] = c2;
                float h = sigf(go) * tanhf(c2);
                hout[(size_t)row * DD2 + dir * DHH + j] = h;
                hOut[b * DHH + j] = h;
            }
        }
        gbar((unsigned)t);
    }
}

// ---------------- attention ----------------
__global__ __launch_bounds__(256) void attention_kernel(
    const float* __restrict__ M, const float* __restrict__ X,
    const float* __restrict__ umask, float* __restrict__ att)
{
    const int b = blockIdx.y;
    const int t0 = blockIdx.x * 16;
    const int tid = threadIdx.x;
    const int ti = tid >> 4, si = tid & 15;

    __shared__ float Ms[128][33];
    __shared__ float Xs[16][33];
    __shared__ float Aa[16][129];
    __shared__ float um[128];
    if (tid < 128) um[tid] = umask[b * SSEQ + tid];
    __syncthreads();

    float acc[8];
#pragma unroll
    for (int u = 0; u < 8; u++) acc[u] = 0.0f;

    for (int k0 = 0; k0 < DD2; k0 += 32) {
        {
            int s = tid >> 1;
            float u = um[s];
            const float* mrow = M + ((size_t)(s * BBS + b)) * DD2 + k0;
#pragma unroll
            for (int i = 0; i < 4; i++) {
                int c = (tid & 1) * 16 + i * 4;
                float4 v = *(const float4*)(mrow + c);
                Ms[s][c] = v.x * u; Ms[s][c + 1] = v.y * u;
                Ms[s][c + 2] = v.z * u; Ms[s][c + 3] = v.w * u;
            }
        }
        if (tid < 128) {
            int r = tid >> 3, c = (tid & 7) * 4;
            float4 v = *(const float4*)(X + ((size_t)((t0 + r) * BBS + b)) * DD2 + k0 + c);
            Xs[r][c] = v.x; Xs[r][c + 1] = v.y; Xs[r][c + 2] = v.z; Xs[r][c + 3] = v.w;
        }
        __syncthreads();
#pragma unroll
        for (int kk = 0; kk < 32; kk++) {
            float xv = Xs[ti][kk];
#pragma unroll
            for (int u = 0; u < 8; u++) acc[u] += xv * Ms[si * 8 + u][kk];
        }
        __syncthreads();
    }

#pragma unroll
    for (int u = 0; u < 8; u++) acc[u] = tanhf(acc[u] * um[si * 8 + u]);
    float mx = -1e30f;
#pragma unroll
    for (int u = 0; u < 8; u++) mx = fmaxf(mx, acc[u]);
    for (int o = 8; o >= 1; o >>= 1) mx = fmaxf(mx, __shfl_xor_sync(0xffffffffu, mx, o, 16));
    float a[8]; float s2 = 0.0f;
#pragma unroll
    for (int u = 0; u < 8; u++) {
        a[u] = expf(acc[u] - mx) * um[si * 8 + u];
        s2 += a[u];
    }
    for (int o = 8; o >= 1; o >>= 1) s2 += __shfl_xor_sync(0xffffffffu, s2, o, 16);
    float inv = 1.0f / s2;
#pragma unroll
    for (int u = 0; u < 8; u++) Aa[ti][si * 8 + u] = a[u] * inv;
    __syncthreads();

    for (int d0 = 0; d0 < DD2; d0 += 32) {
        {
            int s = tid >> 1;
            const float* mrow = M + ((size_t)(s * BBS + b)) * DD2 + d0;
#pragma unroll
            for (int i = 0; i < 4; i++) {
                int c = (tid & 1) * 16 + i * 4;
                float4 v = *(const float4*)(mrow + c);
                Ms[s][c] = v.x; Ms[s][c + 1] = v.y; Ms[s][c + 2] = v.z; Ms[s][c + 3] = v.w;
            }
        }
        __syncthreads();
        int dloc = (tid & 15) * 2;
        float r0 = 0.f, r1 = 0.f;
#pragma unroll 8
        for (int s = 0; s < 128; s++) {
            float al = Aa[ti][s];
            r0 += al * Ms[s][dloc];
            r1 += al * Ms[s][dloc + 1];
        }
        float* orow = att + ((size_t)((t0 + ti) * BBS + b)) * DD2 + d0 + dloc;
        orow[0] = r0; orow[1] = r1;
        __syncthreads();
    }
}

// ---------------- launch ----------------
extern "C" void kernel_launch(void* const* d_in, const int* in_sizes, int n_in,
                              void* d_out, int out_size) {
    const float* feat   = (const float*)d_in[0];
    const int*   ei     = (const int*)d_in[1];
    const int*   et     = (const int*)d_in[2];
    const float* umask  = (const float*)d_in[4];
    const float* Wrel   = (const float*)d_in[5];
    const float* Wroot  = (const float*)d_in[6];
    const float* rb     = (const float*)d_in[7];
    const float* gcWrel = (const float*)d_in[8];
    const float* gcWroot= (const float*)d_in[9];
    const float* gcb    = (const float*)d_in[10];
    const float* Wih0   = (const float*)d_in[11];
    const float* Whh0   = (const float*)d_in[12];
    const float* b0     = (const float*)d_in[13];
    const float* Wih1   = (const float*)d_in[14];
    const float* Whh1   = (const float*)d_in[15];
    const float* b1     = (const float*)d_in[16];
    const float* mattW  = (const float*)d_in[17];
    const float* mattb  = (const float*)d_in[18];
    const float* linW   = (const float*)d_in[19];
    const float* linb   = (const float*)d_in[20];
    float* out = (float*)d_out;

    float *hrel, *out1, *cnt, *agg, *out2, *x0, *g0, *h0, *g1, *Mb, *Xb, *attb, *barp, *hfp;
    u32 *whi, *wlo;
    u64 *as, *bs;
    cudaGetSymbolAddress((void**)&hrel, g_hrel);
    cudaGetSymbolAddress((void**)&out1, g_out1);
    cudaGetSymbolAddress((void**)&cnt,  g_cnt);
    cudaGetSymbolAddress((void**)&agg,  g_agg);
    cudaGetSymbolAddress((void**)&out2, g_out2);
    cudaGetSymbolAddress((void**)&x0,   g_x0);
    cudaGetSymbolAddress((void**)&g0,   g_g0);
    cudaGetSymbolAddress((void**)&h0,   g_h0);
    cudaGetSymbolAddress((void**)&g1,   g_g1);
    cudaGetSymbolAddress((void**)&Mb,   g_M);
    cudaGetSymbolAddress((void**)&Xb,   g_X);
    cudaGetSymbolAddress((void**)&attb, g_att);
    cudaGetSymbolAddress((void**)&barp, (const void*)g_bar);
    cudaGetSymbolAddress((void**)&whi,  g_whi);
    cudaGetSymbolAddress((void**)&wlo,  g_wlo);
    cudaGetSymbolAddress((void**)&hfp,  g_hf);
    cudaGetSymbolAddress((void**)&as,   g_as);
    cudaGetSymbolAddress((void**)&bs,   g_bs);

    cudaFuncSetAttribute(lstm_tc_kernel,
                         cudaFuncAttributeMaxDynamicSharedMemorySize, SMEM_TLSTM);
    cudaFuncSetAttribute(tgemm_kernel<false, false>,
                         cudaFuncAttributeMaxDynamicSharedMemorySize, SMEM_GEMM);
    cudaFuncSetAttribute(tgemm_kernel<true, false>,
                         cudaFuncAttributeMaxDynamicSharedMemorySize, SMEM_GEMM);
    cudaFuncSetAttribute(tgemm_kernel<true, true>,
                         cudaFuncAttributeMaxDynamicSharedMemorySize, SMEM_GEMM);

    const int WN = 2 * GG4 * DHH;
    const int HSF = 2 * 2 * BBS * DHH;
    auto split = [&](const float* src, u64* dst, int n) {
        wsplit2_kernel<<<(n + 255) / 256, 256>>>(src, dst, n);
    };

    // --- graph stage ---
    fill_zero_kernel<<<(NN * RRE + 255) / 256, 256>>>(cnt, NN * RRE);
    fill_zero_kernel<<<(NN * HIDN + 255) / 256, 256>>>(agg, NN * HIDN);
    count_kernel<<<EE / 256, 256>>>(ei, et, cnt);
    split(feat, as, NN * FIN);
    split(Wroot, bs, FIN * HIDN);
    tgemm_kernel<false, false><<<dim3(4, 32, 1), 256, SMEM_GEMM>>>(as, bs, rb, out1,
        NN, HIDN, FIN, 0, 0, 0, 0, 0);
    split(Wrel, bs, RRE * FIN * HIDN);
    tgemm_kernel<false, false><<<dim3(4, 32, RRE), 256, SMEM_GEMM>>>(as, bs, nullptr, hrel,
        NN, HIDN, FIN, 0, (size_t)FIN * HIDN, 0, (size_t)NN * HIDN, 0);
    rgcn_scatter_kernel<<<EE / 4, 256>>>(hrel, ei, et, cnt, out1);
    gconv_scatter_kernel<<<EE / 4, 256>>>(out1, ei, agg);
    split(agg, as, NN * HIDN);
    split(gcWrel, bs, HIDN * HIDN);
    tgemm_kernel<false, false><<<dim3(4, 32, 1), 256, SMEM_GEMM>>>(as, bs, gcb, out2,
        NN, HIDN, HIDN, 0, 0, 0, 0, 0);
    split(out1, as, NN * HIDN);
    split(gcWroot, bs, HIDN * HIDN);
    tgemm_kernel<false, false><<<dim3(4, 32, 1), 256, SMEM_GEMM>>>(as, bs, nullptr, out2,
        NN, HIDN, HIDN, 0, 0, 0, 0, 1);
    concat_kernel<<<NN, 256>>>(feat, out2, x0);

    // --- BiLSTM layer 0 ---
    split(x0, as, NN * DHH);
    split(Wih0, bs, 2 * GG4 * DHH);
    tgemm_kernel<true, false><<<dim3(48, 32, 2), 256, SMEM_GEMM>>>(as, bs, b0, g0,
        NN, GG4, DHH, 0, (size_t)GG4 * DHH, GG4, (size_t)NN * GG4, 0);
    wsplit_kernel<<<(WN + 255) / 256, 256>>>(Whh0, whi, wlo, WN);
    fill_zero_kernel<<<(HSF + 255) / 256, 256>>>(hfp, HSF);
    fill_zero_kernel<<<1, 256>>>(barp, 2);
    lstm_tc_kernel<<<NBLK, 256, SMEM_TLSTM>>>(whi, wlo, g0, hfp, h0);

    // --- BiLSTM layer 1 ---
    split(h0, as, NN * DD2);
    split(Wih1, bs, 2 * GG4 * DD2);
    tgemm_kernel<true, false><<<dim3(48, 32, 2), 256, SMEM_GEMM>>>(as, bs, b1, g1,
        NN, GG4, DD2, 0, (size_t)GG4 * DD2, GG4, (size_t)NN * GG4, 0);
    wsplit_kernel<<<(WN + 255) / 256, 256>>>(Whh1, whi, wlo, WN);
    fill_zero_kernel<<<(HSF + 255) / 256, 256>>>(hfp, HSF);
    fill_zero_kernel<<<1, 256>>>(barp, 2);
    lstm_tc_kernel<<<NBLK, 256, SMEM_TLSTM>>>(whi, wlo, g1, hfp, Mb);

    // --- attention + output ---
    split(Mb, as, NN * DD2);
    split(mattW, bs, DD2 * DD2);
    tgemm_kernel<true, false><<<dim3(24, 32, 1), 256, SMEM_GEMM>>>(as, bs, mattb, Xb,
        NN, DD2, DD2, 0, 0, 0, 0, 0);
    attention_kernel<<<dim3(8, 32), 256>>>(Mb, Xb, umask, attb);
    split(attb, as, NN * DD2);
    split(linW, bs, DHH * DD2);
    tgemm_kernel<true, true><<<dim3(12, 32, 1), 256, SMEM_GEMM>>>(as, bs, linb, out,
        NN, DHH, DD2, 0, 0, 0, 0, 0);
}